// round 1
// baseline (speedup 1.0000x reference)
#include <cuda_runtime.h>
#include <math.h>

// Problem constants: B=4, C=128 (C_SEM), H=W=64, N=4096, MASK half-width 5.

#define NPIX 4096
#define NTOT (4 * NPIX)

// ---------------- scratch (__device__ globals; allocation-free) ----------------
__device__ float g_edge32[4 * 128 * 1024];   // conv1x1(edge_features) at 32x32, [b][c][p32]
__device__ float g_fused32[4 * 128 * 1024];  // conv1x1(fused_features) at 32x32
__device__ float g_xq[4 * 128 * NPIX];       // edge*similarity, c-major   [b][c][p]
__device__ float g_fusedT[4 * 128 * NPIX];   // fused aligned, c-major     [b][c][p]
__device__ float g_v[NTOT * 256];            // sem_val = [sem_raw; fused] [bp][c]
__device__ float g_l2e[NTOT];
__device__ float g_dens[NTOT];
__device__ float g_q[NTOT * 256];            // [bp][o]
__device__ float g_k[NTOT * 256];            // [bp][o]
__device__ float g_ao[NTOT * 256];           // attention output [bp][o]

// ---------------- K0: 1x1 convs at 32x32 (conv commutes with bilinear) ---------
__global__ void conv32_kernel(const float* __restrict__ ef, const float* __restrict__ ff,
                              const float* __restrict__ wa, const float* __restrict__ ba,
                              const float* __restrict__ wfa, const float* __restrict__ bfa) {
    __shared__ float xe[64];
    __shared__ float xf[128];
    int bp = blockIdx.x;            // b*1024 + p32
    int b = bp >> 10, p = bp & 1023;
    int t = threadIdx.x;            // out channel 0..127
    if (t < 64) xe[t] = ef[(b * 64 + t) * 1024 + p];
    xf[t] = ff[(b * 128 + t) * 1024 + p];
    __syncthreads();
    float a = ba[t];
#pragma unroll 8
    for (int ci = 0; ci < 64; ci++) a += wa[t * 64 + ci] * xe[ci];
    g_edge32[(b * 128 + t) * 1024 + p] = a;
    float a2 = bfa[t];
#pragma unroll 8
    for (int ci = 0; ci < 128; ci++) a2 += wfa[t * 128 + ci] * xf[ci];
    g_fused32[(b * 128 + t) * 1024 + p] = a2;
}

// ---------------- K1: bilinear upsample + cosine sim + build X/V ---------------
__global__ void prep_kernel(const float* __restrict__ sem) {
    int bp = blockIdx.x;                     // b*4096 + p
    int b = bp >> 12, p = bp & 4095;
    int oy = p >> 6, ox = p & 63;
    int c = threadIdx.x;                     // channel 0..127

    // half-pixel bilinear (matches jax.image.resize linear / F.interpolate ac=False)
    float sy = oy * 0.5f - 0.25f;
    int y0i = (int)floorf(sy);
    float wy = sy - (float)y0i;
    int y0 = y0i < 0 ? 0 : y0i;
    int y1 = (y0i + 1) > 31 ? 31 : (y0i + 1);
    float sx = ox * 0.5f - 0.25f;
    int x0i = (int)floorf(sx);
    float wx = sx - (float)x0i;
    int x0 = x0i < 0 ? 0 : x0i;
    int x1 = (x0i + 1) > 31 ? 31 : (x0i + 1);

    const float* e32 = g_edge32 + (b * 128 + c) * 1024;
    float ev = (1.f - wy) * ((1.f - wx) * e32[y0 * 32 + x0] + wx * e32[y0 * 32 + x1]) +
               wy * ((1.f - wx) * e32[y1 * 32 + x0] + wx * e32[y1 * 32 + x1]);
    const float* f32 = g_fused32 + (b * 128 + c) * 1024;
    float fv = (1.f - wy) * ((1.f - wx) * f32[y0 * 32 + x0] + wx * f32[y0 * 32 + x1]) +
               wy * ((1.f - wx) * f32[y1 * 32 + x0] + wx * f32[y1 * 32 + x1]);
    float sv = sem[(b * 128 + c) * 4096 + p];

    float a = ev * ev, d = ev * sv, s2 = sv * sv;
#pragma unroll
    for (int o = 16; o; o >>= 1) {
        a  += __shfl_xor_sync(0xffffffffu, a, o);
        d  += __shfl_xor_sync(0xffffffffu, d, o);
        s2 += __shfl_xor_sync(0xffffffffu, s2, o);
    }
    __shared__ float ra[4], rd[4], rs[4];
    int w = c >> 5;
    if ((c & 31) == 0) { ra[w] = a; rd[w] = d; rs[w] = s2; }
    __syncthreads();
    a  = ra[0] + ra[1] + ra[2] + ra[3];
    d  = rd[0] + rd[1] + rd[2] + rd[3];
    s2 = rs[0] + rs[1] + rs[2] + rs[3];
    float l2e = sqrtf(a), l2s = sqrtf(s2);
    float sim = (d / ((l2e + 1e-6f) * (l2s + 1e-6f)) + 1.f) * 0.5f;

    if (c == 0) g_l2e[bp] = l2e;
    g_xq[(b * 128 + c) * 4096 + p] = ev * sim;
    g_fusedT[(b * 128 + c) * 4096 + p] = fv;
    g_v[bp * 256 + c] = sv;
    g_v[bp * 256 + 128 + c] = fv;
}

// ---------------- K2: density = softmax(l2_edge) * N, one block per batch -----
__global__ void density_kernel() {
    __shared__ float red[32];
    __shared__ float red2[32];
    __shared__ float bmax, bsum;
    int b = blockIdx.x, t = threadIdx.x;   // 1024 threads
    float v[4];
    float mx = -1e30f;
#pragma unroll
    for (int i = 0; i < 4; i++) { v[i] = g_l2e[b * 4096 + t + i * 1024]; mx = fmaxf(mx, v[i]); }
#pragma unroll
    for (int d = 16; d; d >>= 1) mx = fmaxf(mx, __shfl_xor_sync(~0u, mx, d));
    if ((t & 31) == 0) red[t >> 5] = mx;
    __syncthreads();
    if (t < 32) {
        float m2 = red[t];
#pragma unroll
        for (int d = 16; d; d >>= 1) m2 = fmaxf(m2, __shfl_xor_sync(~0u, m2, d));
        if (t == 0) bmax = m2;
    }
    __syncthreads();
    float m = bmax;
    float s = 0.f;
#pragma unroll
    for (int i = 0; i < 4; i++) { v[i] = expf(v[i] - m); s += v[i]; }
#pragma unroll
    for (int d = 16; d; d >>= 1) s += __shfl_xor_sync(~0u, s, d);
    if ((t & 31) == 0) red2[t >> 5] = s;
    __syncthreads();
    if (t < 32) {
        float s2 = red2[t];
#pragma unroll
        for (int d = 16; d; d >>= 1) s2 += __shfl_xor_sync(~0u, s2, d);
        if (t == 0) bsum = s2;
    }
    __syncthreads();
    float f = 4096.f / bsum;
#pragma unroll
    for (int i = 0; i < 4; i++) g_dens[b * 4096 + t + i * 1024] = v[i] * f;
}

// ---------------- K3: Q projection GEMM (folded concat: Weff = Wq[:,:128]+Wq[:,128:])
__global__ void gemm_q_kernel(const float* __restrict__ wq, const float* __restrict__ bq) {
    __shared__ float Ws[16][68];
    __shared__ float Xs[16][68];
    __shared__ float Os[64][65];
    int t = threadIdx.x;
    int tx = t & 15, ty = t >> 4;
    int gp0 = blockIdx.x * 64;
    int o0 = blockIdx.y * 64;
    int b = gp0 >> 12;
    int pl = gp0 & 4095;
    float acc[4][4] = {};
    for (int k0 = 0; k0 < 128; k0 += 16) {
        for (int i = t; i < 1024; i += 256) {
            int o = i >> 4, cc = i & 15;
            int row = (o0 + o) * 256 + k0 + cc;
            Ws[cc][o] = wq[row] + wq[row + 128];
        }
        for (int i = t; i < 1024; i += 256) {
            int cc2 = i >> 6, pp = i & 63;
            Xs[cc2][pp] = g_xq[(b * 128 + k0 + cc2) * 4096 + pl + pp];
        }
        __syncthreads();
#pragma unroll
        for (int kk = 0; kk < 16; kk++) {
            float4 wv = *(float4*)&Ws[kk][ty * 4];
            float4 xv = *(float4*)&Xs[kk][tx * 4];
            float w_[4] = {wv.x, wv.y, wv.z, wv.w};
            float x_[4] = {xv.x, xv.y, xv.z, xv.w};
#pragma unroll
            for (int u = 0; u < 4; u++)
#pragma unroll
                for (int v = 0; v < 4; v++) acc[u][v] += w_[u] * x_[v];
        }
        __syncthreads();
    }
#pragma unroll
    for (int u = 0; u < 4; u++) {
        float bias = bq[o0 + ty * 4 + u];
#pragma unroll
        for (int v = 0; v < 4; v++) Os[tx * 4 + v][ty * 4 + u] = acc[u][v] + bias;
    }
    __syncthreads();
    for (int i = t; i < 4096; i += 256) {
        int pp = i >> 6, oo = i & 63;
        g_q[(gp0 + pp) * 256 + o0 + oo] = Os[pp][oo];
    }
}

// ---------------- K4: K projection GEMM (X = [sem*density ; fused]) ------------
__global__ void gemm_k_kernel(const float* __restrict__ sem,
                              const float* __restrict__ wk, const float* __restrict__ bk) {
    __shared__ float Ws[16][68];
    __shared__ float Xs[16][68];
    __shared__ float Os[64][65];
    int t = threadIdx.x;
    int tx = t & 15, ty = t >> 4;
    int gp0 = blockIdx.x * 64;
    int o0 = blockIdx.y * 64;
    int b = gp0 >> 12;
    int pl = gp0 & 4095;
    float acc[4][4] = {};
    for (int k0 = 0; k0 < 256; k0 += 16) {
        for (int i = t; i < 1024; i += 256) {
            int o = i >> 4, cc = i & 15;
            Ws[cc][o] = wk[(o0 + o) * 256 + k0 + cc];
        }
        for (int i = t; i < 1024; i += 256) {
            int cc2 = i >> 6, pp = i & 63;
            int cg = k0 + cc2;
            int gp = pl + pp;
            float xv;
            if (cg < 128)
                xv = sem[(b * 128 + cg) * 4096 + gp] * g_dens[(b << 12) + gp];
            else
                xv = g_fusedT[(b * 128 + cg - 128) * 4096 + gp];
            Xs[cc2][pp] = xv;
        }
        __syncthreads();
#pragma unroll
        for (int kk = 0; kk < 16; kk++) {
            float4 wv = *(float4*)&Ws[kk][ty * 4];
            float4 xv = *(float4*)&Xs[kk][tx * 4];
            float w_[4] = {wv.x, wv.y, wv.z, wv.w};
            float x_[4] = {xv.x, xv.y, xv.z, xv.w};
#pragma unroll
            for (int u = 0; u < 4; u++)
#pragma unroll
                for (int v = 0; v < 4; v++) acc[u][v] += w_[u] * x_[v];
        }
        __syncthreads();
    }
#pragma unroll
    for (int u = 0; u < 4; u++) {
        float bias = bk[o0 + ty * 4 + u];
#pragma unroll
        for (int v = 0; v < 4; v++) Os[tx * 4 + v][ty * 4 + u] = acc[u][v] + bias;
    }
    __syncthreads();
    for (int i = t; i < 4096; i += 256) {
        int pp = i >> 6, oo = i & 63;
        g_k[(gp0 + pp) * 256 + o0 + oo] = Os[pp][oo];
    }
}

// ---------------- K5: windowed attention (exact: outside-window prob == 0) -----
// CTA = 8x4 query tile (32 queries), 512 threads. Union key window <= 18x14 = 252.
// Dynamic smem: q_s[32*256] | S[32*256] | kv[256*134] | mky[256] | mkx[256]
#define ATTN_SMEM ((32 * 256 + 32 * 256 + 256 * 134) * 4 + 256 * 2 * 4)

__global__ void attn_kernel() {
    extern __shared__ float sm[];
    float* q_s = sm;
    float* Ssm = sm + 32 * 256;
    float* kv = Ssm + 32 * 256;
    int* mky = (int*)(kv + 256 * 134);
    int* mkx = mky + 256;

    int t = threadIdx.x;
    int blk = blockIdx.x;
    int b = blk >> 7;
    int tile = blk & 127;
    int tyT = tile >> 4, txT = tile & 15;
    int qy0 = tyT * 8, qx0 = txT * 4;
    int uy0 = qy0 - 5 < 0 ? 0 : qy0 - 5;
    int uy1 = qy0 + 12 > 63 ? 63 : qy0 + 12;
    int ux0 = qx0 - 5 < 0 ? 0 : qx0 - 5;
    int ux1 = qx0 + 8 > 63 ? 63 : qx0 + 8;
    int uw = ux1 - ux0 + 1;
    int M = (uy1 - uy0 + 1) * uw;

    // load Q tile [32][256]
    for (int i = t; i < 32 * 256; i += 512) {
        int qi = i >> 8, cc = i & 255;
        int qy = qy0 + (qi >> 2), qx = qx0 + (qi & 3);
        q_s[i] = g_q[(((b << 12) + (qy << 6) + qx) << 8) + cc];
    }
    if (t < 256) {
        int ry = t / uw;
        mky[t] = uy0 + ry;
        mkx[t] = ux0 + (t - ry * uw);
    }
    __syncthreads();

    int qg = t >> 6;   // 0..7 -> queries {qg, qg+8, qg+16, qg+24}
    int mg = t & 63;   // key slots {mg, mg+64, mg+128, mg+192}

    float acc[4][4] = {};
    for (int ch = 0; ch < 2; ch++) {
        for (int i = t; i < M * 128; i += 512) {
            int r = i >> 7, cc = i & 127;
            int m = (mky[r] << 6) + mkx[r];
            kv[r * 134 + cc] = g_k[((((b << 12) + m)) << 8) + (ch << 7) + cc];
        }
        __syncthreads();
#pragma unroll 2
        for (int cc = 0; cc < 128; cc++) {
            float qv[4], kvv[4];
#pragma unroll
            for (int u = 0; u < 4; u++) qv[u] = q_s[(qg + 8 * u) * 256 + ch * 128 + cc];
#pragma unroll
            for (int j = 0; j < 4; j++) kvv[j] = kv[(mg + 64 * j) * 134 + cc];
#pragma unroll
            for (int u = 0; u < 4; u++)
#pragma unroll
                for (int j = 0; j < 4; j++) acc[u][j] += qv[u] * kvv[j];
        }
        __syncthreads();
    }

    // write scores with window mask (scale = 1/sqrt(256))
#pragma unroll
    for (int u = 0; u < 4; u++) {
        int qi = qg + 8 * u;
        int qy = qy0 + (qi >> 2), qx = qx0 + (qi & 3);
#pragma unroll
        for (int j = 0; j < 4; j++) {
            int s = mg + 64 * j;
            float val = -1e30f;
            if (s < M) {
                int dy = mky[s] - qy; if (dy < 0) dy = -dy;
                int dx = mkx[s] - qx; if (dx < 0) dx = -dx;
                if (dy <= 5 && dx <= 5) val = acc[u][j] * 0.0625f;
            }
            Ssm[qi * 256 + s] = val;
        }
    }
    __syncthreads();

    // softmax: 16 lanes per query (16-aligned groups -> shfl_xor over {8,4,2,1})
    {
        int qi = t >> 4, l = t & 15;
        float v[16];
        float mx = -1e30f;
#pragma unroll
        for (int k = 0; k < 16; k++) { v[k] = Ssm[qi * 256 + l + 16 * k]; mx = fmaxf(mx, v[k]); }
#pragma unroll
        for (int d = 8; d; d >>= 1) mx = fmaxf(mx, __shfl_xor_sync(~0u, mx, d));
        float s = 0.f;
#pragma unroll
        for (int k = 0; k < 16; k++) { v[k] = expf(v[k] - mx); s += v[k]; }
#pragma unroll
        for (int d = 8; d; d >>= 1) s += __shfl_xor_sync(~0u, s, d);
        float inv = 1.f / s;
#pragma unroll
        for (int k = 0; k < 16; k++) Ssm[qi * 256 + l + 16 * k] = v[k] * inv;
    }
    __syncthreads();

    // AV: thread owns (qg: 4 queries) x (2 channels per chunk)
    int cg = t & 63;
    int c0 = cg * 2;
    for (int ch = 0; ch < 2; ch++) {
        for (int i = t; i < M * 128; i += 512) {
            int r = i >> 7, cc = i & 127;
            int m = (mky[r] << 6) + mkx[r];
            kv[r * 134 + cc] = g_v[((((b << 12) + m)) << 8) + (ch << 7) + cc];
        }
        __syncthreads();
        float a0[4] = {}, a1[4] = {};
        for (int s = 0; s < M; s++) {
            float2 vv = *(float2*)&kv[s * 134 + c0];
#pragma unroll
            for (int u = 0; u < 4; u++) {
                float p = Ssm[(qg + 8 * u) * 256 + s];
                a0[u] += p * vv.x;
                a1[u] += p * vv.y;
            }
        }
#pragma unroll
        for (int u = 0; u < 4; u++) {
            int qi = qg + 8 * u;
            int qy = qy0 + (qi >> 2), qx = qx0 + (qi & 3);
            float2 o2 = make_float2(a0[u], a1[u]);
            *(float2*)&g_ao[(((b << 12) + (qy << 6) + qx) << 8) + (ch << 7) + c0] = o2;
        }
        __syncthreads();
    }
}

// ---------------- K6: final fusion GEMM (writes d_out directly) ----------------
__global__ void gemm_f_kernel(const float* __restrict__ wf, const float* __restrict__ bf,
                              float* __restrict__ out) {
    __shared__ float Ws[16][68];
    __shared__ float Xs[16][68];
    int t = threadIdx.x;
    int tx = t & 15, ty = t >> 4;
    int gp0 = blockIdx.x * 64;
    int o0 = blockIdx.y * 64;
    int b = gp0 >> 12;
    int pl = gp0 & 4095;
    float acc[4][4] = {};
    for (int k0 = 0; k0 < 256; k0 += 16) {
        for (int i = t; i < 1024; i += 256) {
            int o = i >> 4, cc = i & 15;
            Ws[cc][o] = wf[(o0 + o) * 256 + k0 + cc];
        }
        for (int i = t; i < 1024; i += 256) {
            int pp = i >> 4, cc = i & 15;
            Xs[cc][pp] = g_ao[(gp0 + pp) * 256 + k0 + cc];
        }
        __syncthreads();
#pragma unroll
        for (int kk = 0; kk < 16; kk++) {
            float4 wv = *(float4*)&Ws[kk][ty * 4];
            float4 xv = *(float4*)&Xs[kk][tx * 4];
            float w_[4] = {wv.x, wv.y, wv.z, wv.w};
            float x_[4] = {xv.x, xv.y, xv.z, xv.w};
#pragma unroll
            for (int u = 0; u < 4; u++)
#pragma unroll
                for (int v = 0; v < 4; v++) acc[u][v] += w_[u] * x_[v];
        }
        __syncthreads();
    }
#pragma unroll
    for (int u = 0; u < 4; u++) {
        int o = o0 + ty * 4 + u;
        float bias = bf[o];
        float4 r = make_float4(acc[u][0] + bias, acc[u][1] + bias,
                               acc[u][2] + bias, acc[u][3] + bias);
        *(float4*)&out[(b * 128 + o) * 4096 + pl + tx * 4] = r;
    }
}

// ---------------- launch --------------------------------------------------------
extern "C" void kernel_launch(void* const* d_in, const int* in_sizes, int n_in,
                              void* d_out, int out_size) {
    const float* ef  = (const float*)d_in[0];
    const float* sem = (const float*)d_in[1];
    const float* ff  = (const float*)d_in[2];
    const float* wa  = (const float*)d_in[3];
    const float* ba  = (const float*)d_in[4];
    const float* wfa = (const float*)d_in[5];
    const float* bfa = (const float*)d_in[6];
    const float* wq  = (const float*)d_in[7];
    const float* bq  = (const float*)d_in[8];
    const float* wk  = (const float*)d_in[9];
    const float* bk  = (const float*)d_in[10];
    const float* wfu = (const float*)d_in[11];
    const float* bfu = (const float*)d_in[12];
    float* out = (float*)d_out;

    conv32_kernel<<<4096, 128>>>(ef, ff, wa, ba, wfa, bfa);
    prep_kernel<<<16384, 128>>>(sem);
    density_kernel<<<4, 1024>>>();
    gemm_q_kernel<<<dim3(256, 4), 256>>>(wq, bq);
    gemm_k_kernel<<<dim3(256, 4), 256>>>(sem, wk, bk);
    cudaFuncSetAttribute(attn_kernel, cudaFuncAttributeMaxDynamicSharedMemorySize, ATTN_SMEM);
    attn_kernel<<<512, 512, ATTN_SMEM>>>();
    gemm_f_kernel<<<dim3(256, 2), 256>>>(wfu, bfu, out);
}